// round 1
// baseline (speedup 1.0000x reference)
#include <cuda_runtime.h>
#include <math.h>

#define B_BATCH 64
#define D_DIM   768
#define L1_N    8192
#define BRANCH  32
#define TOPK    32
#define NCAND   (TOPK * BRANCH)   // 1024

// ---------------- scratch (allocation-free: static __device__ globals) ----
__device__ float g_logits0[B_BATCH * L1_N];        // 2 MB
__device__ int   g_sel[B_BATCH * TOPK];            // sorted ascending group ids
__device__ float g_p0[B_BATCH * TOPK];             // sigmoid(parent logit), aligned with g_sel

// ---------------- Kernel 1: logits0 = x @ W0^T + b0  (f32, exact) ----------
// M=64 (batches), N=8192 (groups), K=768. Block tile 64x64, BK=16,
// 256 threads, 4x4 micro-tile per thread. Grid = 128 blocks.
#define BK 16
__global__ __launch_bounds__(256) void gemm1_kernel(
    const float* __restrict__ x, const float* __restrict__ W0,
    const float* __restrict__ b0)
{
    __shared__ float As[BK][64];      // x tile, transposed [k][m]
    __shared__ float Bs[BK][64 + 4];  // W0 tile, transposed [k][n] (+pad)

    const int n0 = blockIdx.x * 64;
    const int t  = threadIdx.x;
    const int tm = t >> 4;            // 0..15 -> batch quad
    const int tn = t & 15;            // 0..15 -> group quad

    float acc[4][4] = {};

    for (int k0 = 0; k0 < D_DIM; k0 += BK) {
        // load x tile: 64 rows x 16 k — one float4 per thread
        {
            int r  = t >> 2;
            int cc = (t & 3) * 4;
            float4 v = *(const float4*)(x + (size_t)r * D_DIM + k0 + cc);
            As[cc + 0][r] = v.x; As[cc + 1][r] = v.y;
            As[cc + 2][r] = v.z; As[cc + 3][r] = v.w;
        }
        // load W0 tile: 64 rows x 16 k — one float4 per thread
        {
            int r  = t >> 2;
            int cc = (t & 3) * 4;
            float4 v = *(const float4*)(W0 + (size_t)(n0 + r) * D_DIM + k0 + cc);
            Bs[cc + 0][r] = v.x; Bs[cc + 1][r] = v.y;
            Bs[cc + 2][r] = v.z; Bs[cc + 3][r] = v.w;
        }
        __syncthreads();

        #pragma unroll
        for (int k = 0; k < BK; k++) {
            float a[4], b[4];
            *(float4*)a = *(const float4*)&As[k][tm * 4];
            *(float4*)b = *(const float4*)&Bs[k][tn * 4];
            #pragma unroll
            for (int i = 0; i < 4; i++)
                #pragma unroll
                for (int j = 0; j < 4; j++)
                    acc[i][j] = fmaf(a[i], b[j], acc[i][j]);
        }
        __syncthreads();
    }

    #pragma unroll
    for (int i = 0; i < 4; i++) {
        int m = tm * 4 + i;
        #pragma unroll
        for (int j = 0; j < 4; j++) {
            int n = n0 + tn * 4 + j;
            g_logits0[(size_t)m * L1_N + n] = acc[i][j] + b0[n];
        }
    }
}

// ---------------- Kernel 2: per-row top-32 (stable, lowest-index ties), ----
// then sort selected indices ascending; store sigmoid(parent logit).
__global__ __launch_bounds__(256) void topk_kernel()
{
    __shared__ float vals[L1_N];      // 32 KB
    __shared__ float rv[256];
    __shared__ int   ri[256];
    __shared__ int   pIdx[TOPK];
    __shared__ float pVal[TOPK];

    const int b = blockIdx.x;
    const int t = threadIdx.x;

    for (int i = t; i < L1_N; i += 256) vals[i] = g_logits0[(size_t)b * L1_N + i];
    __syncthreads();

    for (int it = 0; it < TOPK; it++) {
        float bv = -INFINITY; int bi = L1_N;
        for (int i = t; i < L1_N; i += 256) {
            float v = vals[i];
            if (v > bv) { bv = v; bi = i; }   // strided ascending -> ties keep lowest idx
        }
        rv[t] = bv; ri[t] = bi;
        __syncthreads();
        for (int s = 128; s > 0; s >>= 1) {
            if (t < s) {
                if (rv[t + s] > rv[t] || (rv[t + s] == rv[t] && ri[t + s] < ri[t])) {
                    rv[t] = rv[t + s]; ri[t] = ri[t + s];
                }
            }
            __syncthreads();
        }
        if (t == 0) {
            pIdx[it] = ri[0]; pVal[it] = rv[0];
            vals[ri[0]] = -INFINITY;
        }
        __syncthreads();
    }

    if (t == 0) {
        // insertion sort ascending by group index (matches jnp.sort(sel))
        for (int i = 1; i < TOPK; i++) {
            int ki = pIdx[i]; float kv = pVal[i]; int j = i - 1;
            while (j >= 0 && pIdx[j] > ki) {
                pIdx[j + 1] = pIdx[j]; pVal[j + 1] = pVal[j]; j--;
            }
            pIdx[j + 1] = ki; pVal[j + 1] = kv;
        }
        for (int i = 0; i < TOPK; i++) {
            g_sel[b * TOPK + i] = pIdx[i];
            g_p0[b * TOPK + i]  = 1.0f / (1.0f + expf(-pVal[i]));
        }
    }
}

// ---------------- Kernel 3: gather-score leaves. One warp per candidate. ---
// probs = p0[parent] * sigmoid(x . W1[leaf] + b1[leaf]); also emit cand, mask.
__global__ __launch_bounds__(256) void leaf_kernel(
    const float* __restrict__ x, const float* __restrict__ W1,
    const float* __restrict__ b1,
    float* __restrict__ probs_out, float* __restrict__ cand_out,
    float* __restrict__ mask_out)
{
    __shared__ float xs[D_DIM];

    const int b  = blockIdx.x >> 7;        // 128 blocks per batch
    const int c0 = (blockIdx.x & 127) * 8; // 8 candidates (warps) per block
    const int t  = threadIdx.x;

    // stage x[b] into smem (192 float4)
    for (int i = t; i < D_DIM / 4; i += 256)
        ((float4*)xs)[i] = ((const float4*)(x + (size_t)b * D_DIM))[i];
    __syncthreads();

    const int w    = t >> 5;
    const int lane = t & 31;
    const int c    = c0 + w;               // candidate 0..1023
    const int i    = c >> 5;               // beam slot
    const int j    = c & 31;               // child within group
    const int g    = g_sel[b * TOPK + i];
    const int leaf = g * BRANCH + j;

    const float4* wr = (const float4*)(W1 + (size_t)leaf * D_DIM);
    const float4* xr = (const float4*)xs;

    float s = 0.0f;
    #pragma unroll
    for (int q = 0; q < 6; q++) {          // 6 * 32 lanes * 4 = 768
        float4 wv = wr[lane + 32 * q];
        float4 xv = xr[lane + 32 * q];
        s = fmaf(wv.x, xv.x, s);
        s = fmaf(wv.y, xv.y, s);
        s = fmaf(wv.z, xv.z, s);
        s = fmaf(wv.w, xv.w, s);
    }
    #pragma unroll
    for (int off = 16; off; off >>= 1)
        s += __shfl_xor_sync(0xffffffffu, s, off);

    if (lane == 0) {
        float logit = s + b1[leaf];
        float p = g_p0[b * TOPK + i] * (1.0f / (1.0f + expf(-logit)));
        int idx = b * NCAND + c;
        probs_out[idx] = p;
        if (cand_out) cand_out[idx] = (float)leaf;
        if (mask_out) mask_out[idx] = 1.0f;
    }
}

// ---------------- launch ----------------
extern "C" void kernel_launch(void* const* d_in, const int* in_sizes, int n_in,
                              void* d_out, int out_size)
{
    const float* x  = (const float*)d_in[0];
    const float* W0 = (const float*)d_in[1];
    const float* b0 = (const float*)d_in[2];
    const float* W1 = (const float*)d_in[3];
    const float* b1 = (const float*)d_in[4];
    float* out = (float*)d_out;

    const int total = B_BATCH * NCAND;  // 65536
    float* probs = out;
    float* cand  = (out_size >= 2 * total) ? out + total     : nullptr;
    float* mask  = (out_size >= 3 * total) ? out + 2 * total : nullptr;

    gemm1_kernel<<<L1_N / 64, 256>>>(x, W0, b0);
    topk_kernel<<<B_BATCH, 256>>>();
    leaf_kernel<<<B_BATCH * 128, 256>>>(x, W1, b1, probs, cand, mask);
}

// round 3
// speedup vs baseline: 1.0433x; 1.0433x over previous
#include <cuda_runtime.h>
#include <math.h>

#define B_BATCH 64
#define D_DIM   768
#define L1_N    8192
#define BRANCH  32
#define TOPK    32
#define NCAND   (TOPK * BRANCH)   // 1024
#define KSPLIT  4
#define KCH     (D_DIM / KSPLIT)  // 192
#define BK      16

// ---------------- scratch (allocation-free: static __device__ globals) ----
__device__ float g_part[KSPLIT][B_BATCH * L1_N];   // 8 MB K-split partials
__device__ int   g_sel[B_BATCH * TOPK];            // sorted ascending group ids
__device__ float g_p0[B_BATCH * TOPK];             // sigmoid(parent logit)

// ---------------- packed f32x2 FMA (sm_103a FFMA2) ------------------------
__device__ __forceinline__ unsigned long long ffma2(
    unsigned long long a, unsigned long long b, unsigned long long c)
{
    unsigned long long d;
    asm("fma.rn.f32x2 %0, %1, %2, %3;" : "=l"(d) : "l"(a), "l"(b), "l"(c));
    return d;
}
union F4U { float4 f4; unsigned long long u[2]; float f[4]; };
union UF2 { unsigned long long u; float f[2]; };

// ---------------- Kernel 1: partial GEMM  logits0 = x @ W0^T --------------
// M=64, N=8192, K=768 split 4 ways. Block tile 64x64xKCH, 256 threads,
// 4x4 micro-tile as 2 m-pairs x 4 n, all FMAs as FFMA2.
// B tile stored column-duplicated so b-operands alias register pairs.
// Row pad: 128+4=132 floats = 528 B, multiple of 16 -> LDS.128 stays aligned.
__global__ __launch_bounds__(256) void gemm1_kernel(
    const float* __restrict__ x, const float* __restrict__ W0,
    const float* __restrict__ b0)
{
    __shared__ float As[BK][64];        // x tile [k][m]   (256 B rows)
    __shared__ float Bs[BK][128 + 4];   // W0 tile duplicated: [k][2n+{0,1}]

    const int n0 = blockIdx.x * 64;
    const int ks = blockIdx.y;
    const int kbase = ks * KCH;
    const int t  = threadIdx.x;
    const int tm = t >> 4;
    const int tn = t & 15;

    unsigned long long acc[2][4] = {};  // [m-pair][n]

    for (int k0 = 0; k0 < KCH; k0 += BK) {
        {   // x tile: 64 m x 16 k
            int r  = t >> 2;
            int cc = (t & 3) * 4;
            float4 v = *(const float4*)(x + (size_t)r * D_DIM + kbase + k0 + cc);
            As[cc + 0][r] = v.x; As[cc + 1][r] = v.y;
            As[cc + 2][r] = v.z; As[cc + 3][r] = v.w;
        }
        {   // W0 tile, duplicated columns
            int r  = t >> 2;
            int cc = (t & 3) * 4;
            float4 v = *(const float4*)(W0 + (size_t)(n0 + r) * D_DIM + kbase + k0 + cc);
            Bs[cc + 0][2 * r] = v.x; Bs[cc + 0][2 * r + 1] = v.x;
            Bs[cc + 1][2 * r] = v.y; Bs[cc + 1][2 * r + 1] = v.y;
            Bs[cc + 2][2 * r] = v.z; Bs[cc + 2][2 * r + 1] = v.z;
            Bs[cc + 3][2 * r] = v.w; Bs[cc + 3][2 * r + 1] = v.w;
        }
        __syncthreads();

        #pragma unroll
        for (int k = 0; k < BK; k++) {
            F4U a;  a.f4  = *(const float4*)&As[k][tm * 4];       // (m0,m1),(m2,m3)
            F4U bl; bl.f4 = *(const float4*)&Bs[k][tn * 8];       // (n0,n0),(n1,n1)
            F4U bh; bh.f4 = *(const float4*)&Bs[k][tn * 8 + 4];   // (n2,n2),(n3,n3)
            acc[0][0] = ffma2(a.u[0], bl.u[0], acc[0][0]);
            acc[0][1] = ffma2(a.u[0], bl.u[1], acc[0][1]);
            acc[0][2] = ffma2(a.u[0], bh.u[0], acc[0][2]);
            acc[0][3] = ffma2(a.u[0], bh.u[1], acc[0][3]);
            acc[1][0] = ffma2(a.u[1], bl.u[0], acc[1][0]);
            acc[1][1] = ffma2(a.u[1], bl.u[1], acc[1][1]);
            acc[1][2] = ffma2(a.u[1], bh.u[0], acc[1][2]);
            acc[1][3] = ffma2(a.u[1], bh.u[1], acc[1][3]);
        }
        __syncthreads();
    }

    #pragma unroll
    for (int p = 0; p < 2; p++) {
        #pragma unroll
        for (int j = 0; j < 4; j++) {
            UF2 v; v.u = acc[p][j];
            int n = n0 + tn * 4 + j;
            int m0 = tm * 4 + 2 * p;
            float bias = (ks == 0) ? b0[n] : 0.0f;
            g_part[ks][(size_t)m0 * L1_N + n]       = v.f[0] + bias;
            g_part[ks][(size_t)(m0 + 1) * L1_N + n] = v.f[1] + bias;
        }
    }
}

// ---------------- Kernel 2: incremental top-32 ----------------------------
// Key = ordered-float(val) in high 32b, (MAX-idx) low 32b -> single u64 max
// gives highest value with lowest-index tie-break.
__device__ __forceinline__ unsigned long long mkkey(float v, int idx)
{
    unsigned u = __float_as_uint(v);
    u = (u & 0x80000000u) ? ~u : (u | 0x80000000u);
    return ((unsigned long long)u << 32) | (unsigned)(0x7FFFFFFF - idx);
}

__global__ __launch_bounds__(256) void topk_kernel()
{
    __shared__ float vals[L1_N];                  // 32 KB
    __shared__ unsigned long long skey[256];
    __shared__ unsigned long long wkey[8];
    __shared__ int   pIdx[TOPK];
    __shared__ float pVal[TOPK];

    const int b = blockIdx.x;
    const int t = threadIdx.x;
    const int w = t >> 5, lane = t & 31;

    for (int i = t; i < L1_N; i += 256) {
        size_t o = (size_t)b * L1_N + i;
        vals[i] = (g_part[0][o] + g_part[1][o]) + (g_part[2][o] + g_part[3][o]);
    }
    __syncthreads();

    // per-thread local max over strided slice {t, t+256, ...}
    unsigned long long kk = 0;
    #pragma unroll
    for (int j = 0; j < L1_N / 256; j++) {
        int idx = t + j * 256;
        unsigned long long c = mkkey(vals[idx], idx);
        if (c > kk) kk = c;
    }
    skey[t] = kk;
    __syncthreads();

    for (int it = 0; it < TOPK; it++) {
        unsigned long long xk = skey[t];
        #pragma unroll
        for (int off = 16; off; off >>= 1) {
            unsigned long long o2 = __shfl_xor_sync(0xffffffffu, xk, off);
            if (o2 > xk) xk = o2;
        }
        if (lane == 0) wkey[w] = xk;
        __syncthreads();
        if (t == 0) {
            unsigned long long best = wkey[0];
            #pragma unroll
            for (int i2 = 1; i2 < 8; i2++) if (wkey[i2] > best) best = wkey[i2];
            int idx = 0x7FFFFFFF - (int)(unsigned)(best & 0xFFFFFFFFull);
            pIdx[it] = idx; pVal[it] = vals[idx];
            vals[idx] = -INFINITY;
            int s = idx & 255;                  // only this slice changed
            unsigned long long nk = 0;
            for (int j = 0; j < L1_N / 256; j++) {
                int id2 = s + j * 256;
                unsigned long long c = mkkey(vals[id2], id2);
                if (c > nk) nk = c;
            }
            skey[s] = nk;
        }
        __syncthreads();
    }

    if (t == 0) {
        // ascending index sort (matches jnp.sort(sel))
        for (int i = 1; i < TOPK; i++) {
            int ki = pIdx[i]; float kv = pVal[i]; int j = i - 1;
            while (j >= 0 && pIdx[j] > ki) {
                pIdx[j + 1] = pIdx[j]; pVal[j + 1] = pVal[j]; j--;
            }
            pIdx[j + 1] = ki; pVal[j + 1] = kv;
        }
        for (int i = 0; i < TOPK; i++) {
            g_sel[b * TOPK + i] = pIdx[i];
            g_p0[b * TOPK + i]  = 1.0f / (1.0f + expf(-pVal[i]));
        }
    }
}

// ---------------- Kernel 3: gather-score leaves (warp per candidate) ------
__global__ __launch_bounds__(256) void leaf_kernel(
    const float* __restrict__ x, const float* __restrict__ W1,
    const float* __restrict__ b1,
    float* __restrict__ probs_out, float* __restrict__ cand_out,
    float* __restrict__ mask_out)
{
    __shared__ float xs[D_DIM];

    const int b  = blockIdx.x >> 7;
    const int c0 = (blockIdx.x & 127) * 8;
    const int t  = threadIdx.x;

    for (int i = t; i < D_DIM / 4; i += 256)
        ((float4*)xs)[i] = ((const float4*)(x + (size_t)b * D_DIM))[i];
    __syncthreads();

    const int w    = t >> 5;
    const int lane = t & 31;
    const int c    = c0 + w;
    const int i    = c >> 5;
    const int j    = c & 31;
    const int g    = g_sel[b * TOPK + i];
    const int leaf = g * BRANCH + j;

    const float4* wr = (const float4*)(W1 + (size_t)leaf * D_DIM);
    const float4* xr = (const float4*)xs;

    unsigned long long s0 = 0, s1 = 0;          // two packed accumulators
    #pragma unroll
    for (int q = 0; q < 6; q++) {
        F4U wv; wv.f4 = __ldcs(wr + lane + 32 * q);   // streaming: one-shot data
        F4U xv; xv.f4 = xr[lane + 32 * q];
        s0 = ffma2(wv.u[0], xv.u[0], s0);
        s1 = ffma2(wv.u[1], xv.u[1], s1);
    }
    UF2 u0; u0.u = s0;
    UF2 u1; u1.u = s1;
    float s = (u0.f[0] + u0.f[1]) + (u1.f[0] + u1.f[1]);

    #pragma unroll
    for (int off = 16; off; off >>= 1)
        s += __shfl_xor_sync(0xffffffffu, s, off);

    if (lane == 0) {
        float logit = s + b1[leaf];
        float p = g_p0[b * TOPK + i] * (1.0f / (1.0f + expf(-logit)));
        int idx = b * NCAND + c;
        probs_out[idx] = p;
        if (cand_out) cand_out[idx] = (float)leaf;
        if (mask_out) mask_out[idx] = 1.0f;
    }
}

// ---------------- launch ----------------
extern "C" void kernel_launch(void* const* d_in, const int* in_sizes, int n_in,
                              void* d_out, int out_size)
{
    const float* x  = (const float*)d_in[0];
    const float* W0 = (const float*)d_in[1];
    const float* b0 = (const float*)d_in[2];
    const float* W1 = (const float*)d_in[3];
    const float* b1 = (const float*)d_in[4];
    float* out = (float*)d_out;

    const int total = B_BATCH * NCAND;  // 65536
    float* probs = out;
    float* cand  = (out_size >= 2 * total) ? out + total     : nullptr;
    float* mask  = (out_size >= 3 * total) ? out + 2 * total : nullptr;

    gemm1_kernel<<<dim3(L1_N / 64, KSPLIT), 256>>>(x, W0, b0);
    topk_kernel<<<B_BATCH, 256>>>();
    leaf_kernel<<<B_BATCH * 128, 256>>>(x, W1, b1, probs, cand, mask);
}

// round 4
// speedup vs baseline: 1.2478x; 1.1960x over previous
#include <cuda_runtime.h>
#include <math.h>

#define B_BATCH 64
#define D_DIM   768
#define L1_N    8192
#define BRANCH  32
#define TOPK    32
#define NCAND   (TOPK * BRANCH)   // 1024
#define KSPLIT  8
#define KCH     (D_DIM / KSPLIT)  // 96
#define BK      16
#define NT      128               // gemm1 n-tile

// ---------------- scratch (allocation-free: static __device__ globals) ----
__device__ float g_part[KSPLIT][B_BATCH * L1_N];   // 16 MB K-split partials
__device__ int   g_sel[B_BATCH * TOPK];            // sorted ascending group ids
__device__ float g_p0[B_BATCH * TOPK];             // sigmoid(parent logit)

// ---------------- packed f32x2 FMA (sm_103a FFMA2) ------------------------
__device__ __forceinline__ unsigned long long ffma2(
    unsigned long long a, unsigned long long b, unsigned long long c)
{
    unsigned long long d;
    asm("fma.rn.f32x2 %0, %1, %2, %3;" : "=l"(d) : "l"(a), "l"(b), "l"(c));
    return d;
}
union F4U { float4 f4; unsigned long long u[2]; float f[4]; };
union UF2 { unsigned long long u; float f[2]; };

// ---------------- Kernel 1: partial GEMM  logits0 = x @ W0^T --------------
// M=64, N=8192, K=768 split 8 ways. Block tile 64x128xKCH, 256 threads.
// Thread tile 4m x 8n; m-pairs packed for FFMA2, b duplicated in smem as
// (b,b) pairs. n strided (tn + 16j) so every b LDS.64 has 8B lane stride
// -> conflict-free. As rows 68 floats (272B, 16B mult, 2-way STS);
// Bsd rows 260 floats (1040B, 16B mult, 2-way STS).
__global__ __launch_bounds__(256) void gemm1_kernel(
    const float* __restrict__ x, const float* __restrict__ W0,
    const float* __restrict__ b0)
{
    __shared__ float As[BK][68];        // x tile [k][m]
    __shared__ float Bsd[BK][260];      // W0 tile duplicated [k][2n|2n+1]

    const int n0    = blockIdx.x * NT;
    const int ks    = blockIdx.y;
    const int kbase = ks * KCH;
    const int t  = threadIdx.x;
    const int tm = t >> 4;              // 0..15 -> m quad
    const int tn = t & 15;              // 0..15 -> n lane

    unsigned long long acc[2][8] = {};  // [m-pair][n-slot]

    for (int k0 = 0; k0 < KCH; k0 += BK) {
        {   // x tile: 64 m x 16 k, one float4 per thread
            int r  = t >> 2;
            int cc = (t & 3) * 4;
            float4 v = *(const float4*)(x + (size_t)r * D_DIM + kbase + k0 + cc);
            As[cc + 0][r] = v.x; As[cc + 1][r] = v.y;
            As[cc + 2][r] = v.z; As[cc + 3][r] = v.w;
        }
        {   // W0 tile: 128 n x 16 k, two float4 per thread, duplicated store
            int r   = t >> 1;           // 0..127 local n
            int ccb = (t & 1) * 8;
            #pragma unroll
            for (int h = 0; h < 2; h++) {
                int cc = ccb + h * 4;
                float4 v = *(const float4*)(W0 + (size_t)(n0 + r) * D_DIM + kbase + k0 + cc);
                Bsd[cc + 0][2*r] = v.x; Bsd[cc + 0][2*r + 1] = v.x;
                Bsd[cc + 1][2*r] = v.y; Bsd[cc + 1][2*r + 1] = v.y;
                Bsd[cc + 2][2*r] = v.z; Bsd[cc + 2][2*r + 1] = v.z;
                Bsd[cc + 3][2*r] = v.w; Bsd[cc + 3][2*r + 1] = v.w;
            }
        }
        __syncthreads();

        #pragma unroll
        for (int k = 0; k < BK; k++) {
            F4U a; a.f4 = *(const float4*)&As[k][tm * 4];   // (m0,m1),(m2,m3)
            unsigned long long bb[8];
            #pragma unroll
            for (int j = 0; j < 8; j++)
                bb[j] = *(const unsigned long long*)&Bsd[k][2 * (tn + 16 * j)];
            #pragma unroll
            for (int j = 0; j < 8; j++) {
                acc[0][j] = ffma2(a.u[0], bb[j], acc[0][j]);
                acc[1][j] = ffma2(a.u[1], bb[j], acc[1][j]);
            }
        }
        __syncthreads();
    }

    #pragma unroll
    for (int j = 0; j < 8; j++) {
        int n = n0 + tn + 16 * j;
        float bias = (ks == 0) ? b0[n] : 0.0f;
        #pragma unroll
        for (int p = 0; p < 2; p++) {
            UF2 v; v.u = acc[p][j];
            int m0 = tm * 4 + 2 * p;
            g_part[ks][(size_t)m0 * L1_N + n]       = v.f[0] + bias;
            g_part[ks][(size_t)(m0 + 1) * L1_N + n] = v.f[1] + bias;
        }
    }
}

// ---------------- Kernel 2: incremental top-32 ----------------------------
// Key = ordered-float(val) hi 32b, (MAX-idx) lo 32b -> u64 max = highest
// value with lowest-index tie-break.
__device__ __forceinline__ unsigned long long mkkey(float v, int idx)
{
    unsigned u = __float_as_uint(v);
    u = (u & 0x80000000u) ? ~u : (u | 0x80000000u);
    return ((unsigned long long)u << 32) | (unsigned)(0x7FFFFFFF - idx);
}

__global__ __launch_bounds__(256) void topk_kernel()
{
    __shared__ float vals[L1_N];                  // 32 KB
    __shared__ unsigned long long skey[256];
    __shared__ unsigned long long wkey[8];
    __shared__ int   pIdx[TOPK];
    __shared__ float pVal[TOPK];

    const int b = blockIdx.x;
    const int t = threadIdx.x;
    const int w = t >> 5, lane = t & 31;

    for (int i = t; i < L1_N; i += 256) {
        size_t o = (size_t)b * L1_N + i;
        float s = 0.0f;
        #pragma unroll
        for (int p = 0; p < KSPLIT; p++) s += g_part[p][o];
        vals[i] = s;
    }
    __syncthreads();

    unsigned long long kk = 0;
    #pragma unroll
    for (int j = 0; j < L1_N / 256; j++) {
        int idx = t + j * 256;
        unsigned long long c = mkkey(vals[idx], idx);
        if (c > kk) kk = c;
    }
    skey[t] = kk;
    __syncthreads();

    for (int it = 0; it < TOPK; it++) {
        unsigned long long xk = skey[t];
        #pragma unroll
        for (int off = 16; off; off >>= 1) {
            unsigned long long o2 = __shfl_xor_sync(0xffffffffu, xk, off);
            if (o2 > xk) xk = o2;
        }
        if (lane == 0) wkey[w] = xk;
        __syncthreads();
        if (t == 0) {
            unsigned long long best = wkey[0];
            #pragma unroll
            for (int i2 = 1; i2 < 8; i2++) if (wkey[i2] > best) best = wkey[i2];
            int idx = 0x7FFFFFFF - (int)(unsigned)(best & 0xFFFFFFFFull);
            pIdx[it] = idx; pVal[it] = vals[idx];
            vals[idx] = -INFINITY;
            int s = idx & 255;                  // only this slice changed
            unsigned long long nk = 0;
            for (int j = 0; j < L1_N / 256; j++) {
                int id2 = s + j * 256;
                unsigned long long c = mkkey(vals[id2], id2);
                if (c > nk) nk = c;
            }
            skey[s] = nk;
        }
        __syncthreads();
    }

    if (t == 0) {
        for (int i = 1; i < TOPK; i++) {   // ascending index sort
            int ki = pIdx[i]; float kv = pVal[i]; int j = i - 1;
            while (j >= 0 && pIdx[j] > ki) {
                pIdx[j + 1] = pIdx[j]; pVal[j + 1] = pVal[j]; j--;
            }
            pIdx[j + 1] = ki; pVal[j + 1] = kv;
        }
        for (int i = 0; i < TOPK; i++) {
            g_sel[b * TOPK + i] = pIdx[i];
            g_p0[b * TOPK + i]  = 1.0f / (1.0f + expf(-pVal[i]));
        }
    }
}

// ---------------- Kernel 3: gather-score leaves ---------------------------
// 2 candidates per warp, all 12 LDG.128 issued before FMAs (MLP=12).
__global__ __launch_bounds__(256) void leaf_kernel(
    const float* __restrict__ x, const float* __restrict__ W1,
    const float* __restrict__ b1,
    float* __restrict__ probs_out, float* __restrict__ cand_out,
    float* __restrict__ mask_out)
{
    __shared__ float xs[D_DIM];

    const int b  = blockIdx.x >> 6;         // 64 cblocks per batch
    const int c0 = (blockIdx.x & 63) * 16;  // 16 candidates per block
    const int t  = threadIdx.x;

    for (int i = t; i < D_DIM / 4; i += 256)
        ((float4*)xs)[i] = ((const float4*)(x + (size_t)b * D_DIM))[i];
    __syncthreads();

    const int w    = t >> 5;
    const int lane = t & 31;
    const int cA   = c0 + w;
    const int cB   = c0 + w + 8;
    const int iA = cA >> 5, jA = cA & 31;
    const int iB = cB >> 5, jB = cB & 31;
    const int leafA = g_sel[b * TOPK + iA] * BRANCH + jA;
    const int leafB = g_sel[b * TOPK + iB] * BRANCH + jB;

    const float4* wrA = (const float4*)(W1 + (size_t)leafA * D_DIM);
    const float4* wrB = (const float4*)(W1 + (size_t)leafB * D_DIM);
    const float4* xr  = (const float4*)xs;

    F4U wa[6], wb[6];
    #pragma unroll
    for (int q = 0; q < 6; q++) wa[q].f4 = __ldcs(wrA + lane + 32 * q);
    #pragma unroll
    for (int q = 0; q < 6; q++) wb[q].f4 = __ldcs(wrB + lane + 32 * q);

    unsigned long long a0 = 0, a1 = 0, b0acc = 0, b1acc = 0;
    #pragma unroll
    for (int q = 0; q < 6; q++) {
        F4U xv; xv.f4 = xr[lane + 32 * q];
        a0    = ffma2(wa[q].u[0], xv.u[0], a0);
        a1    = ffma2(wa[q].u[1], xv.u[1], a1);
        b0acc = ffma2(wb[q].u[0], xv.u[0], b0acc);
        b1acc = ffma2(wb[q].u[1], xv.u[1], b1acc);
    }
    UF2 ua0; ua0.u = a0;  UF2 ua1; ua1.u = a1;
    UF2 ub0; ub0.u = b0acc; UF2 ub1; ub1.u = b1acc;
    float sA = (ua0.f[0] + ua0.f[1]) + (ua1.f[0] + ua1.f[1]);
    float sB = (ub0.f[0] + ub0.f[1]) + (ub1.f[0] + ub1.f[1]);

    #pragma unroll
    for (int off = 16; off; off >>= 1) {
        sA += __shfl_xor_sync(0xffffffffu, sA, off);
        sB += __shfl_xor_sync(0xffffffffu, sB, off);
    }

    if (lane == 0) {
        float lgA = sA + b1[leafA];
        float lgB = sB + b1[leafB];
        float pA = g_p0[b * TOPK + iA] * (1.0f / (1.0f + expf(-lgA)));
        float pB = g_p0[b * TOPK + iB] * (1.0f / (1.0f + expf(-lgB)));
        int idxA = b * NCAND + cA;
        int idxB = b * NCAND + cB;
        probs_out[idxA] = pA;
        probs_out[idxB] = pB;
        if (cand_out) { cand_out[idxA] = (float)leafA; cand_out[idxB] = (float)leafB; }
        if (mask_out) { mask_out[idxA] = 1.0f;         mask_out[idxB] = 1.0f; }
    }
}

// ---------------- launch ----------------
extern "C" void kernel_launch(void* const* d_in, const int* in_sizes, int n_in,
                              void* d_out, int out_size)
{
    const float* x  = (const float*)d_in[0];
    const float* W0 = (const float*)d_in[1];
    const float* b0 = (const float*)d_in[2];
    const float* W1 = (const float*)d_in[3];
    const float* b1 = (const float*)d_in[4];
    float* out = (float*)d_out;

    const int total = B_BATCH * NCAND;  // 65536
    float* probs = out;
    float* cand  = (out_size >= 2 * total) ? out + total     : nullptr;
    float* mask  = (out_size >= 3 * total) ? out + 2 * total : nullptr;

    gemm1_kernel<<<dim3(L1_N / NT, KSPLIT), 256>>>(x, W0, b0);
    topk_kernel<<<B_BATCH, 256>>>();
    leaf_kernel<<<B_BATCH * 64, 256>>>(x, W1, b1, probs, cand, mask);
}

// round 5
// speedup vs baseline: 1.3825x; 1.1080x over previous
#include <cuda_runtime.h>
#include <math.h>

#define B_BATCH 64
#define D_DIM   768
#define L1_N    8192
#define BRANCH  32
#define TOPK    32
#define NCAND   (TOPK * BRANCH)   // 1024
#define KSPLIT  8
#define KCH     (D_DIM / KSPLIT)  // 96
#define BK      16
#define NT      128               // gemm1 n-tile

// ---------------- scratch (allocation-free: static __device__ globals) ----
__device__ float g_part[KSPLIT][B_BATCH * L1_N];   // 16 MB K-split partials
__device__ int   g_sel[B_BATCH * TOPK];
__device__ float g_p0[B_BATCH * TOPK];

// ---------------- packed f32x2 FMA (sm_103a FFMA2) ------------------------
__device__ __forceinline__ unsigned long long ffma2(
    unsigned long long a, unsigned long long b, unsigned long long c)
{
    unsigned long long d;
    asm("fma.rn.f32x2 %0, %1, %2, %3;" : "=l"(d) : "l"(a), "l"(b), "l"(c));
    return d;
}
union F4U { float4 f4; unsigned long long u[2]; float f[4]; };
union UF2 { unsigned long long u; float f[2]; };

// ---------------- Kernel 1: partial GEMM  logits0 = x @ W0^T --------------
// 64m x 128n block tile, 256 threads, thread tile 4m x 8n. Accumulator
// pairs run along n; A is duplicated in smem as (a,a) pairs (tiny operand),
// B stays natural. b LDS.64 at n=2tn+32j: 8B lane stride -> conflict-free.
// Register prefetch overlaps next tile's LDG with compute.
__global__ __launch_bounds__(256) void gemm1_kernel(
    const float* __restrict__ x, const float* __restrict__ W0,
    const float* __restrict__ b0)
{
    __shared__ float Ad[BK][132];   // (a,a) pairs: [k][2m|2m+1]  (528B rows)
    __shared__ float Bs[BK][132];   // natural    : [k][n]

    const int n0    = blockIdx.x * NT;
    const int ks    = blockIdx.y;
    const int kbase = ks * KCH;
    const int t  = threadIdx.x;
    const int tm = t >> 4;          // 0..15
    const int tn = t & 15;          // 0..15

    const int ar = t >> 2;          // x row   0..63
    const int ac = (t & 3) * 4;     // x k col
    const int br = t >> 1;          // W0 row  0..127
    const int bc = (t & 1) * 8;     // W0 k col base

    unsigned long long acc[4][4] = {};   // [m][n-pair]

    const float* xp = x  + (size_t)ar * D_DIM + kbase + ac;
    const float* bp = W0 + (size_t)(n0 + br) * D_DIM + kbase + bc;

    float4 av  = *(const float4*)xp;
    float4 bv0 = *(const float4*)bp;
    float4 bv1 = *(const float4*)(bp + 4);

    for (int k0 = 0; k0 < KCH; k0 += BK) {
        // stage prefetched regs into smem
        #pragma unroll
        for (int i = 0; i < 4; i++) {
            float v = (i == 0) ? av.x : (i == 1) ? av.y : (i == 2) ? av.z : av.w;
            *(float2*)&Ad[ac + i][2 * ar] = make_float2(v, v);
        }
        Bs[bc + 0][br] = bv0.x; Bs[bc + 1][br] = bv0.y;
        Bs[bc + 2][br] = bv0.z; Bs[bc + 3][br] = bv0.w;
        Bs[bc + 4][br] = bv1.x; Bs[bc + 5][br] = bv1.y;
        Bs[bc + 6][br] = bv1.z; Bs[bc + 7][br] = bv1.w;
        __syncthreads();

        if (k0 + BK < KCH) {            // prefetch next tile
            av  = *(const float4*)(xp + k0 + BK);
            bv0 = *(const float4*)(bp + k0 + BK);
            bv1 = *(const float4*)(bp + k0 + BK + 4);
        }

        #pragma unroll
        for (int k = 0; k < BK; k++) {
            F4U a01, a23;
            a01.f4 = *(const float4*)&Ad[k][tm * 8];       // (a0,a0,a1,a1)
            a23.f4 = *(const float4*)&Ad[k][tm * 8 + 4];   // (a2,a2,a3,a3)
            unsigned long long bb[4];
            #pragma unroll
            for (int j = 0; j < 4; j++)
                bb[j] = *(const unsigned long long*)&Bs[k][2 * tn + 32 * j];
            #pragma unroll
            for (int j = 0; j < 4; j++) {
                acc[0][j] = ffma2(a01.u[0], bb[j], acc[0][j]);
                acc[1][j] = ffma2(a01.u[1], bb[j], acc[1][j]);
                acc[2][j] = ffma2(a23.u[0], bb[j], acc[2][j]);
                acc[3][j] = ffma2(a23.u[1], bb[j], acc[3][j]);
            }
        }
        __syncthreads();
    }

    #pragma unroll
    for (int j = 0; j < 4; j++) {
        int n = n0 + 2 * tn + 32 * j;
        float bia0 = (ks == 0) ? b0[n]     : 0.0f;
        float bia1 = (ks == 0) ? b0[n + 1] : 0.0f;
        #pragma unroll
        for (int m = 0; m < 4; m++) {
            UF2 v; v.u = acc[m][j];
            int mg = tm * 4 + m;
            *(float2*)&g_part[ks][(size_t)mg * L1_N + n] =
                make_float2(v.f[0] + bia0, v.f[1] + bia1);
        }
    }
}

// ---------------- Kernel 2: top-32, warp-resident selection loop ----------
__device__ __forceinline__ unsigned long long mkkey(float v, int idx)
{
    unsigned u = __float_as_uint(v);
    u = (u & 0x80000000u) ? ~u : (u | 0x80000000u);
    return ((unsigned long long)u << 32) | (unsigned)(0x7FFFFFFF - idx);
}
__device__ __forceinline__ float keyval(unsigned long long k)
{
    unsigned u = (unsigned)(k >> 32);
    u = (u & 0x80000000u) ? (u & 0x7FFFFFFFu) : ~u;
    return __uint_as_float(u);
}

__global__ __launch_bounds__(256) void topk_kernel()
{
    __shared__ float vals[L1_N];                  // 32 KB
    __shared__ unsigned long long skey[256];
    __shared__ int   pIdx[TOPK];
    __shared__ float pVal[TOPK];

    const int b = blockIdx.x;
    const int t = threadIdx.x;

    for (int i = t; i < L1_N; i += 256) {
        size_t o = (size_t)b * L1_N + i;
        float s = 0.0f;
        #pragma unroll
        for (int p = 0; p < KSPLIT; p++) s += g_part[p][o];
        vals[i] = s;
    }
    __syncthreads();

    // slice s = {i : i % 256 == s}, 32 elements each
    {
        unsigned long long kk = 0;
        #pragma unroll
        for (int j = 0; j < L1_N / 256; j++) {
            int idx = t + j * 256;
            unsigned long long c = mkkey(vals[idx], idx);
            if (c > kk) kk = c;
        }
        skey[t] = kk;
    }
    __syncthreads();

    if (t < 32) {
        unsigned long long kr[8];
        #pragma unroll
        for (int r = 0; r < 8; r++) kr[r] = skey[t + 32 * r];

        for (int it = 0; it < TOPK; it++) {
            unsigned long long best = kr[0];
            #pragma unroll
            for (int r = 1; r < 8; r++) if (kr[r] > best) best = kr[r];
            unsigned long long m = best;
            #pragma unroll
            for (int off = 16; off; off >>= 1) {
                unsigned long long o = __shfl_xor_sync(0xffffffffu, m, off);
                if (o > m) m = o;
            }
            int idx = 0x7FFFFFFF - (int)(unsigned)(m & 0xFFFFFFFFull);
            int s   = idx & 255;
            if (t == (s & 31)) {                // owning lane refreshes its slice
                vals[idx] = -INFINITY;
                unsigned long long nk = 0;
                #pragma unroll
                for (int j = 0; j < L1_N / 256; j++) {
                    int id2 = s + j * 256;
                    unsigned long long c = mkkey(vals[id2], id2);
                    if (c > nk) nk = c;
                }
                kr[s >> 5] = nk;
            }
            if (t == 0) { pIdx[it] = idx; pVal[it] = keyval(m); }
            __syncwarp();
        }

        if (t == 0) {
            for (int i = 1; i < TOPK; i++) {    // ascending index sort
                int ki = pIdx[i]; float kv = pVal[i]; int j = i - 1;
                while (j >= 0 && pIdx[j] > ki) {
                    pIdx[j + 1] = pIdx[j]; pVal[j + 1] = pVal[j]; j--;
                }
                pIdx[j + 1] = ki; pVal[j + 1] = kv;
            }
            for (int i = 0; i < TOPK; i++) {
                g_sel[b * TOPK + i] = pIdx[i];
                g_p0[b * TOPK + i]  = 1.0f / (1.0f + expf(-pVal[i]));
            }
        }
    }
}

// ---------------- Kernel 3: gather-score leaves (2 cand/warp, MLP=12) -----
__global__ __launch_bounds__(256) void leaf_kernel(
    const float* __restrict__ x, const float* __restrict__ W1,
    const float* __restrict__ b1,
    float* __restrict__ probs_out, float* __restrict__ cand_out,
    float* __restrict__ mask_out)
{
    __shared__ float xs[D_DIM];

    const int b  = blockIdx.x >> 6;
    const int c0 = (blockIdx.x & 63) * 16;
    const int t  = threadIdx.x;

    for (int i = t; i < D_DIM / 4; i += 256)
        ((float4*)xs)[i] = ((const float4*)(x + (size_t)b * D_DIM))[i];
    __syncthreads();

    const int w    = t >> 5;
    const int lane = t & 31;
    const int cA   = c0 + w;
    const int cB   = c0 + w + 8;
    const int iA = cA >> 5, jA = cA & 31;
    const int iB = cB >> 5, jB = cB & 31;
    const int leafA = g_sel[b * TOPK + iA] * BRANCH + jA;
    const int leafB = g_sel[b * TOPK + iB] * BRANCH + jB;

    const float4* wrA = (const float4*)(W1 + (size_t)leafA * D_DIM);
    const float4* wrB = (const float4*)(W1 + (size_t)leafB * D_DIM);
    const float4* xr  = (const float4*)xs;

    F4U wa[6], wb[6];
    #pragma unroll
    for (int q = 0; q < 6; q++) wa[q].f4 = __ldcs(wrA + lane + 32 * q);
    #pragma unroll
    for (int q = 0; q < 6; q++) wb[q].f4 = __ldcs(wrB + lane + 32 * q);

    unsigned long long a0 = 0, a1 = 0, b0acc = 0, b1acc = 0;
    #pragma unroll
    for (int q = 0; q < 6; q++) {
        F4U xv; xv.f4 = xr[lane + 32 * q];
        a0    = ffma2(wa[q].u[0], xv.u[0], a0);
        a1    = ffma2(wa[q].u[1], xv.u[1], a1);
        b0acc = ffma2(wb[q].u[0], xv.u[0], b0acc);
        b1acc = ffma2(wb[q].u[1], xv.u[1], b1acc);
    }
    UF2 ua0; ua0.u = a0;    UF2 ua1; ua1.u = a1;
    UF2 ub0; ub0.u = b0acc; UF2 ub1; ub1.u = b1acc;
    float sA = (ua0.f[0] + ua0.f[1]) + (ua1.f[0] + ua1.f[1]);
    float sB = (ub0.f[0] + ub0.f[1]) + (ub1.f[0] + ub1.f[1]);

    #pragma unroll
    for (int off = 16; off; off >>= 1) {
        sA += __shfl_xor_sync(0xffffffffu, sA, off);
        sB += __shfl_xor_sync(0xffffffffu, sB, off);
    }

    if (lane == 0) {
        float lgA = sA + b1[leafA];
        float lgB = sB + b1[leafB];
        float pA = g_p0[b * TOPK + iA] * (1.0f / (1.0f + expf(-lgA)));
        float pB = g_p0[b * TOPK + iB] * (1.0f / (1.0f + expf(-lgB)));
        int idxA = b * NCAND + cA;
        int idxB = b * NCAND + cB;
        probs_out[idxA] = pA;
        probs_out[idxB] = pB;
        if (cand_out) { cand_out[idxA] = (float)leafA; cand_out[idxB] = (float)leafB; }
        if (mask_out) { mask_out[idxA] = 1.0f;         mask_out[idxB] = 1.0f; }
    }
}

// ---------------- launch ----------------
extern "C" void kernel_launch(void* const* d_in, const int* in_sizes, int n_in,
                              void* d_out, int out_size)
{
    const float* x  = (const float*)d_in[0];
    const float* W0 = (const float*)d_in[1];
    const float* b0 = (const float*)d_in[2];
    const float* W1 = (const float*)d_in[3];
    const float* b1 = (const float*)d_in[4];
    float* out = (float*)d_out;

    const int total = B_BATCH * NCAND;  // 65536
    float* probs = out;
    float* cand  = (out_size >= 2 * total) ? out + total     : nullptr;
    float* mask  = (out_size >= 3 * total) ? out + 2 * total : nullptr;

    gemm1_kernel<<<dim3(L1_N / NT, KSPLIT), 256>>>(x, W0, b0);
    topk_kernel<<<B_BATCH, 256>>>();
    leaf_kernel<<<B_BATCH * 64, 256>>>(x, W1, b1, probs, cand, mask);
}